// round 10
// baseline (speedup 1.0000x reference)
#include <cuda_runtime.h>
#include <cuda_bf16.h>

// ContrastPreservedChromaEnhancement — pointwise over (16,3,1024,1024) fp32.
// R9: 62.0us bench / 56.7us ncu, DRAM=77.7%, occ=51% (regs 45). Lesson: BW is
// bound by occ*MLP (in-flight bytes/SM), not per-thread MLP. This round:
// keep 6 front-batched LDG.128 but force occ back up via launch_bounds(256,6)
// (<=42 regs, 48 warps/SM), and shorten live ranges by storing group A before
// computing group B.

#define HW4  (1024 * 1024 / 4)   // 262144 = 2^18 vec4 groups per plane

__device__ __forceinline__ void enhance_px(float r, float g, float b,
                                           float& ro, float& go, float& bo) {
    // RGB -> YCbCr (BT.709)
    float y  = fmaf(0.2126f, r, fmaf(0.7152f, g, 0.0722f * b));
    float cb = fmaf(-0.1146f, r, fmaf(-0.3854f, g, 0.5f * b));
    float cr = fmaf(0.5f, r, fmaf(-0.4542f, g, -0.0458f * b));

    float c2 = fmaf(cb, cb, cr * cr);        // chroma^2 (unscaled)

    // ---- fast atan2(cr, cb), degree-7 minimax ----
    float ax = fabsf(cb), ay = fabsf(cr);
    float mx = fmaxf(ax, ay);
    float mn = fminf(ax, ay);
    // guard 0/0 via clamped denominator (avoids extra add in the hot path)
    float q  = mn * __frcp_rn(fmaxf(mx, 1e-30f));   // [0,1]
    float q2 = q * q;
    float p  = fmaf(q2, -0.0851330f, 0.1801410f);
    p = fmaf(q2, p, -0.3302995f);
    p = fmaf(q2, p,  0.9998660f);
    float a = p * q;                          // atan(q)
    a = (ay > ax) ? (1.57079632679f - a) : a; // octant swap
    a = (cb < 0.0f) ? (3.14159265359f - a) : a;
    a = (cr < 0.0f) ? -a : a;                 // atan2 in [-pi, pi]
    float hs = a * 0.95492965855f;            // hue/60 in [-3, 3]

    // ---- closed-form interpolated params (signed-hue identity) ----
    float w   = (hs >= 0.0f) ? hs : (-1.0f - hs);
    float t   = fmaxf(0.0f, fminf(w, 2.0f));  // lerped k
    float s   = __saturatef(w - 1.0f);        // lerped [k==2]
    float a1h = fmaf(-0.05f, t, 0.25f);       // a1/2
    float a1  = a1h + a1h;                    // a1 == a3
    float a2  = fmaf(-0.1f, t, 1.2f);
    float t3p = fmaf(8.6274510e-5f, s, 8.6274510e-4f);  // term3/255

    // ---- delta luma ----
    float llt = __logf(y + 1e-6f) + 0.1f;     // log(y255/255 + 1e-6) + 0.1
    float t1  = __powf(c2 * 65025.0f, a1h);   // chroma255 ^ a1
    float t2  = fmaf(a2, llt, a1);            // a2*llt + a3
    float yo  = __saturatef(fmaf(t1 * t2, t3p, y));

    // ---- YCbCr -> RGB, chroma * 1.2 ----
    float cbo = cb * 1.2f;
    float cro = cr * 1.2f;
    ro = __saturatef(fmaf(1.5748f, cro, yo));
    go = __saturatef(fmaf(-0.1873f, cbo, fmaf(-0.4681f, cro, yo)));
    bo = __saturatef(fmaf(1.8556f, cbo, yo));
}

__global__ void __launch_bounds__(256, 6)
cpce_kernel(const float* __restrict__ x, float* __restrict__ out) {
    // Block covers 512 consecutive vec4 groups (512 | 2^18 -> single batch).
    int g0 = blockIdx.x * 512 + threadIdx.x;
    int bi = g0 >> 18;                         // batch index
    int p0 = g0 & (HW4 - 1);                   // vec4 index in plane

    const float4* xin  = reinterpret_cast<const float4*>(x)  + (size_t)bi * 3 * HW4 + p0;
    float4*       xout = reinterpret_cast<float4*>(out)      + (size_t)bi * 3 * HW4 + p0;

    // Front-batch all 6 loads (MLP=6)
    float4 rA = __ldcs(xin);
    float4 rB = __ldcs(xin + 256);
    float4 gA = __ldcs(xin + HW4);
    float4 gB = __ldcs(xin + HW4 + 256);
    float4 bA = __ldcs(xin + 2 * HW4);
    float4 bB = __ldcs(xin + 2 * HW4 + 256);

    // Group A: compute + store immediately (shortens live ranges -> fewer regs)
    float4 roA, goA, boA;
    enhance_px(rA.x, gA.x, bA.x, roA.x, goA.x, boA.x);
    enhance_px(rA.y, gA.y, bA.y, roA.y, goA.y, boA.y);
    enhance_px(rA.z, gA.z, bA.z, roA.z, goA.z, boA.z);
    enhance_px(rA.w, gA.w, bA.w, roA.w, goA.w, boA.w);
    __stcs(xout,               roA);
    __stcs(xout + HW4,         goA);
    __stcs(xout + 2 * HW4,     boA);

    // Group B
    float4 roB, goB, boB;
    enhance_px(rB.x, gB.x, bB.x, roB.x, goB.x, boB.x);
    enhance_px(rB.y, gB.y, bB.y, roB.y, goB.y, boB.y);
    enhance_px(rB.z, gB.z, bB.z, roB.z, goB.z, boB.z);
    enhance_px(rB.w, gB.w, bB.w, roB.w, goB.w, boB.w);
    __stcs(xout + 256,           roB);
    __stcs(xout + HW4 + 256,     goB);
    __stcs(xout + 2 * HW4 + 256, boB);
}

extern "C" void kernel_launch(void* const* d_in, const int* in_sizes, int n_in,
                              void* d_out, int out_size) {
    const float* x = (const float*)d_in[0];
    float* out = (float*)d_out;

    int nvec    = in_sizes[0] / 12;     // 4,194,304 vec4 groups
    int blocks  = nvec / 512;           // 8192 blocks, exact cover
    cpce_kernel<<<blocks, 256>>>(x, out);
}